// round 3
// baseline (speedup 1.0000x reference)
#include <cuda_runtime.h>

// Shapes fixed by the problem: [B=4, C=32, H=1024, W=1024] fp32 -> [B,H,W] fp32
#define CCH 32
#define HH  1024
#define WW  1024
#define RAD 25   // kernel_radius = W // 40 = 25 (window = 51)
#define RPB 4    // rows per block in kernel A

// 16 MB scratch for channel-summed + box-w'd intermediate
__device__ float g_scratch[4 * HH * WW];

// ---------------------------------------------------------------------------
// Kernel A: per (b, 4-row tile) — gradient magnitude, channel sum, box-w.
// 256 threads; each thread owns 4 consecutive w (float4) for all 4 rows.
// The "top" neighbor row is kept in registers across the inner row loop, so
// each input row is loaded (R+1)/R = 1.25x instead of 2x.
// NO min-blocks launch_bounds — let occupancy float high (round-2 lesson).
// ---------------------------------------------------------------------------
__global__ __launch_bounds__(256) void grad_boxw_kernel(const float* __restrict__ x) {
    const int h0   = blockIdx.x * RPB;
    const int b    = blockIdx.y;
    const int tid  = threadIdx.x;
    const int lane = tid & 31;
    const int wid  = tid >> 5;
    const int w0   = tid << 2;

    const float* xb = x + (size_t)b * CCH * HH * WW;

    float acc[RPB][4];
    #pragma unroll
    for (int r = 0; r < RPB; ++r)
        acc[r][0] = acc[r][1] = acc[r][2] = acc[r][3] = 0.f;

    for (int c = 0; c < CCH; ++c) {
        const float* base = xb + (size_t)c * HH * WW;

        float4 prev;
        if (h0 > 0) prev = *reinterpret_cast<const float4*>(base + (size_t)(h0 - 1) * WW + w0);
        else        prev = make_float4(0.f, 0.f, 0.f, 0.f);

        #pragma unroll
        for (int r = 0; r < RPB; ++r) {
            const float* row = base + (size_t)(h0 + r) * WW;
            float4 cur = *reinterpret_cast<const float4*>(row + w0);

            float left = __shfl_up_sync(0xffffffffu, cur.w, 1);
            if (lane == 0) left = (w0 > 0) ? row[w0 - 1] : 0.f;

            float dx0 = left  - cur.x;
            float dx1 = cur.x - cur.y;
            float dx2 = cur.y - cur.z;
            float dx3 = cur.z - cur.w;
            float dy0 = prev.x - cur.x;
            float dy1 = prev.y - cur.y;
            float dy2 = prev.z - cur.z;
            float dy3 = prev.w - cur.w;

            float s0 = dx0 * dx0 + dy0 * dy0;
            float s1 = dx1 * dx1 + dy1 * dy1;
            float s2 = dx2 * dx2 + dy2 * dy2;
            float s3 = dx3 * dx3 + dy3 * dy3;

            acc[r][0] += (s0 > 0.f) ? s0 * rsqrtf(s0) : 0.f;
            acc[r][1] += (s1 > 0.f) ? s1 * rsqrtf(s1) : 0.f;
            acc[r][2] += (s2 > 0.f) ? s2 * rsqrtf(s2) : 0.f;
            acc[r][3] += (s3 > 0.f) ? s3 * rsqrtf(s3) : 0.f;

            prev = cur;
        }
    }

    // ---- per-row block prefix sum + box-w, RPB rows sequentially ----
    __shared__ float S[WW + 1];
    __shared__ float wsum[8];

    float* gb = g_scratch + (size_t)b * HH * WW;

    #pragma unroll 1
    for (int r = 0; r < RPB; ++r) {
        float p0 = acc[r][0];
        float p1 = p0 + acc[r][1];
        float p2 = p1 + acc[r][2];
        float p3 = p2 + acc[r][3];
        float t  = p3;

        // inclusive warp scan of t
        float sc = t;
        #pragma unroll
        for (int o = 1; o < 32; o <<= 1) {
            float v = __shfl_up_sync(0xffffffffu, sc, o);
            if (lane >= o) sc += v;
        }
        if (lane == 31) wsum[wid] = sc;
        __syncthreads();
        if (wid == 0) {
            float wv = (lane < 8) ? wsum[lane] : 0.f;
            float ws = wv;
            #pragma unroll
            for (int o = 1; o < 8; o <<= 1) {
                float v = __shfl_up_sync(0xffffffffu, ws, o);
                if (lane >= o) ws += v;
            }
            if (lane < 8) wsum[lane] = ws - wv;  // exclusive warp offsets
        }
        __syncthreads();

        float bofs = wsum[wid] + (sc - t);  // exclusive offset for this thread
        if (tid == 0) S[0] = 0.f;
        S[w0 + 1] = bofs + p0;
        S[w0 + 2] = bofs + p1;
        S[w0 + 3] = bofs + p2;
        S[w0 + 4] = bofs + p3;
        __syncthreads();

        float* grow = gb + (size_t)(h0 + r) * WW;
        #pragma unroll
        for (int i = 0; i < 4; ++i) {
            int w  = w0 + i;
            int lo = max(0, w - RAD);
            int hi = min(WW - 1, w + RAD);
            grow[w] = S[hi + 1] - S[lo];
        }
        __syncthreads();   // protect S/wsum reuse in next iteration
    }
}

// ---------------------------------------------------------------------------
// Kernel B: box filter along h (sliding window, float4 columns, coalesced)
// 128-thread blocks; grid = (W4/128, HH/HT, B) = 512 blocks for SM spread.
// 4-way unrolled window init breaks the serial FADD chain (MLP/ILP).
// ---------------------------------------------------------------------------
#define HT 16
#define W4 (WW / 4)
__global__ __launch_bounds__(128) void boxh_kernel(float* __restrict__ out) {
    const int c4 = blockIdx.x * 128 + threadIdx.x;   // float4 column index
    const int h0 = blockIdx.y * HT;
    const int b  = blockIdx.z;

    const float4* gp = reinterpret_cast<const float4*>(g_scratch + (size_t)b * HH * WW) + c4;
    float4*       op = reinterpret_cast<float4*>(out + (size_t)b * HH * WW) + c4;

    const int jlo = max(0, h0 - RAD);
    const int jhi = min(HH - 1, h0 + RAD);

    float4 t0 = make_float4(0.f, 0.f, 0.f, 0.f);
    float4 t1 = make_float4(0.f, 0.f, 0.f, 0.f);
    float4 t2 = make_float4(0.f, 0.f, 0.f, 0.f);
    float4 t3 = make_float4(0.f, 0.f, 0.f, 0.f);

    int j = jlo;
    for (; j + 3 <= jhi; j += 4) {
        float4 v0 = gp[(size_t)(j + 0) * W4];
        float4 v1 = gp[(size_t)(j + 1) * W4];
        float4 v2 = gp[(size_t)(j + 2) * W4];
        float4 v3 = gp[(size_t)(j + 3) * W4];
        t0.x += v0.x; t0.y += v0.y; t0.z += v0.z; t0.w += v0.w;
        t1.x += v1.x; t1.y += v1.y; t1.z += v1.z; t1.w += v1.w;
        t2.x += v2.x; t2.y += v2.y; t2.z += v2.z; t2.w += v2.w;
        t3.x += v3.x; t3.y += v3.y; t3.z += v3.z; t3.w += v3.w;
    }
    for (; j <= jhi; ++j) {
        float4 v = gp[(size_t)j * W4];
        t0.x += v.x; t0.y += v.y; t0.z += v.z; t0.w += v.w;
    }

    float4 s;
    s.x = (t0.x + t1.x) + (t2.x + t3.x);
    s.y = (t0.y + t1.y) + (t2.y + t3.y);
    s.z = (t0.z + t1.z) + (t2.z + t3.z);
    s.w = (t0.w + t1.w) + (t2.w + t3.w);

    #pragma unroll
    for (int i = 0; i < HT; ++i) {
        const int h = h0 + i;
        op[(size_t)h * W4] = s;
        const int add = h + RAD + 1;
        const int sub = h - RAD;
        if (add < HH) {
            float4 v = gp[(size_t)add * W4];
            s.x += v.x; s.y += v.y; s.z += v.z; s.w += v.w;
        }
        if (sub >= 0) {
            float4 v = gp[(size_t)sub * W4];
            s.x -= v.x; s.y -= v.y; s.z -= v.z; s.w -= v.w;
        }
    }
}

// ---------------------------------------------------------------------------

extern "C" void kernel_launch(void* const* d_in, const int* in_sizes, int n_in,
                              void* d_out, int out_size) {
    const float* x = (const float*)d_in[0];
    float* out = (float*)d_out;

    const int n = in_sizes[0];
    const int B = n / (CCH * HH * WW);   // 4

    dim3 gridA(HH / RPB, B);
    grad_boxw_kernel<<<gridA, 256>>>(x);

    dim3 gridB(W4 / 128, HH / HT, B);
    boxh_kernel<<<gridB, 128>>>(out);
}

// round 4
// speedup vs baseline: 1.1568x; 1.1568x over previous
#include <cuda_runtime.h>

// Shapes fixed by the problem: [B=4, C=32, H=1024, W=1024] fp32 -> [B,H,W] fp32
#define CCH 32
#define HH  1024
#define WW  1024
#define RAD 25   // kernel_radius = W // 40 = 25 (window = 51)
#define RPB 4    // rows per block in kernel A

// 16 MB scratch for channel-summed + box-w'd intermediate
__device__ float g_scratch[4 * HH * WW];

// ---------------------------------------------------------------------------
// Kernel A: per (b, 4-row tile) — gradient magnitude, channel sum, box-w.
// 256 threads; each thread owns 4 consecutive w (float4) for all 4 rows.
// NO shuffles in the hot loop (convergence insts block LDG batching): the
// left neighbor comes from a scalar LDG that hits the already-fetched lines.
// Loads are issued in a dedicated front-batch (prev + 4 cur + 4 left = 9
// independent LDGs) before any compute, maximizing MLP.
// ---------------------------------------------------------------------------
__global__ __launch_bounds__(256) void grad_boxw_kernel(const float* __restrict__ x) {
    const int h0   = blockIdx.x * RPB;
    const int b    = blockIdx.y;
    const int tid  = threadIdx.x;
    const int lane = tid & 31;
    const int wid  = tid >> 5;
    const int w0   = tid << 2;

    const float* xb = x + (size_t)b * CCH * HH * WW;

    float acc[RPB][4];
    #pragma unroll
    for (int r = 0; r < RPB; ++r)
        acc[r][0] = acc[r][1] = acc[r][2] = acc[r][3] = 0.f;

    #pragma unroll 2
    for (int c = 0; c < CCH; ++c) {
        const float* base = xb + (size_t)c * HH * WW;

        // ---- front-batched loads (all independent) ----
        float4 prev;
        if (h0 > 0) prev = *reinterpret_cast<const float4*>(base + (size_t)(h0 - 1) * WW + w0);
        else        prev = make_float4(0.f, 0.f, 0.f, 0.f);

        float4 cur[RPB];
        float  lft[RPB];
        #pragma unroll
        for (int r = 0; r < RPB; ++r)
            cur[r] = *reinterpret_cast<const float4*>(base + (size_t)(h0 + r) * WW + w0);
        #pragma unroll
        for (int r = 0; r < RPB; ++r)
            lft[r] = (w0 > 0) ? base[(size_t)(h0 + r) * WW + w0 - 1] : 0.f;

        // ---- compute ----
        #pragma unroll
        for (int r = 0; r < RPB; ++r) {
            float4 cu = cur[r];

            float dx0 = lft[r] - cu.x;
            float dx1 = cu.x - cu.y;
            float dx2 = cu.y - cu.z;
            float dx3 = cu.z - cu.w;
            float dy0 = prev.x - cu.x;
            float dy1 = prev.y - cu.y;
            float dy2 = prev.z - cu.z;
            float dy3 = prev.w - cu.w;

            float s0 = dx0 * dx0 + dy0 * dy0;
            float s1 = dx1 * dx1 + dy1 * dy1;
            float s2 = dx2 * dx2 + dy2 * dy2;
            float s3 = dx3 * dx3 + dy3 * dy3;

            acc[r][0] += (s0 > 0.f) ? s0 * rsqrtf(s0) : 0.f;
            acc[r][1] += (s1 > 0.f) ? s1 * rsqrtf(s1) : 0.f;
            acc[r][2] += (s2 > 0.f) ? s2 * rsqrtf(s2) : 0.f;
            acc[r][3] += (s3 > 0.f) ? s3 * rsqrtf(s3) : 0.f;

            prev = cu;
        }
    }

    // ---- per-row block prefix sum + box-w, RPB rows sequentially ----
    __shared__ float S[WW + 1];
    __shared__ float wsum[8];

    float* gb = g_scratch + (size_t)b * HH * WW;

    #pragma unroll 1
    for (int r = 0; r < RPB; ++r) {
        float p0 = acc[r][0];
        float p1 = p0 + acc[r][1];
        float p2 = p1 + acc[r][2];
        float p3 = p2 + acc[r][3];
        float t  = p3;

        // inclusive warp scan of t
        float sc = t;
        #pragma unroll
        for (int o = 1; o < 32; o <<= 1) {
            float v = __shfl_up_sync(0xffffffffu, sc, o);
            if (lane >= o) sc += v;
        }
        if (lane == 31) wsum[wid] = sc;
        __syncthreads();
        if (wid == 0) {
            float wv = (lane < 8) ? wsum[lane] : 0.f;
            float ws = wv;
            #pragma unroll
            for (int o = 1; o < 8; o <<= 1) {
                float v = __shfl_up_sync(0xffffffffu, ws, o);
                if (lane >= o) ws += v;
            }
            if (lane < 8) wsum[lane] = ws - wv;  // exclusive warp offsets
        }
        __syncthreads();

        float bofs = wsum[wid] + (sc - t);  // exclusive offset for this thread
        if (tid == 0) S[0] = 0.f;
        S[w0 + 1] = bofs + p0;
        S[w0 + 2] = bofs + p1;
        S[w0 + 3] = bofs + p2;
        S[w0 + 4] = bofs + p3;
        __syncthreads();

        float* grow = gb + (size_t)(h0 + r) * WW;
        #pragma unroll
        for (int i = 0; i < 4; ++i) {
            int w  = w0 + i;
            int lo = max(0, w - RAD);
            int hi = min(WW - 1, w + RAD);
            grow[w] = S[hi + 1] - S[lo];
        }
        __syncthreads();   // protect S/wsum reuse in next iteration
    }
}

// ---------------------------------------------------------------------------
// Kernel B: box filter along h (sliding window, float2 columns, coalesced)
// 256-thread blocks, HT=16: 512 blocks x 8 warps = 4096 warps (~27/SM),
// double round-3's warp count — the kernel is L2-latency-bound (scratch is
// L2-resident), so warps in flight are the lever.
// ---------------------------------------------------------------------------
#define HT 16
#define W2 (WW / 2)
__global__ __launch_bounds__(256) void boxh_kernel(float* __restrict__ out) {
    const int c2 = blockIdx.x * 256 + threadIdx.x;   // float2 column index
    const int h0 = blockIdx.y * HT;
    const int b  = blockIdx.z;

    const float2* gp = reinterpret_cast<const float2*>(g_scratch + (size_t)b * HH * WW) + c2;
    float2*       op = reinterpret_cast<float2*>(out + (size_t)b * HH * WW) + c2;

    const int jlo = max(0, h0 - RAD);
    const int jhi = min(HH - 1, h0 + RAD);

    float2 t0 = make_float2(0.f, 0.f);
    float2 t1 = make_float2(0.f, 0.f);
    float2 t2 = make_float2(0.f, 0.f);
    float2 t3 = make_float2(0.f, 0.f);

    int j = jlo;
    for (; j + 3 <= jhi; j += 4) {
        float2 v0 = gp[(size_t)(j + 0) * W2];
        float2 v1 = gp[(size_t)(j + 1) * W2];
        float2 v2 = gp[(size_t)(j + 2) * W2];
        float2 v3 = gp[(size_t)(j + 3) * W2];
        t0.x += v0.x; t0.y += v0.y;
        t1.x += v1.x; t1.y += v1.y;
        t2.x += v2.x; t2.y += v2.y;
        t3.x += v3.x; t3.y += v3.y;
    }
    for (; j <= jhi; ++j) {
        float2 v = gp[(size_t)j * W2];
        t0.x += v.x; t0.y += v.y;
    }

    float2 s;
    s.x = (t0.x + t1.x) + (t2.x + t3.x);
    s.y = (t0.y + t1.y) + (t2.y + t3.y);

    #pragma unroll
    for (int i = 0; i < HT; ++i) {
        const int h = h0 + i;
        op[(size_t)h * W2] = s;
        const int add = h + RAD + 1;
        const int sub = h - RAD;
        if (add < HH) {
            float2 v = gp[(size_t)add * W2];
            s.x += v.x; s.y += v.y;
        }
        if (sub >= 0) {
            float2 v = gp[(size_t)sub * W2];
            s.x -= v.x; s.y -= v.y;
        }
    }
}

// ---------------------------------------------------------------------------

extern "C" void kernel_launch(void* const* d_in, const int* in_sizes, int n_in,
                              void* d_out, int out_size) {
    const float* x = (const float*)d_in[0];
    float* out = (float*)d_out;

    const int n = in_sizes[0];
    const int B = n / (CCH * HH * WW);   // 4

    dim3 gridA(HH / RPB, B);
    grad_boxw_kernel<<<gridA, 256>>>(x);

    dim3 gridB(W2 / 256, HH / HT, B);
    boxh_kernel<<<gridB, 256>>>(out);
}

// round 5
// speedup vs baseline: 1.5428x; 1.3336x over previous
#include <cuda_runtime.h>

// Shapes fixed by the problem: [B=4, C=32, H=1024, W=1024] fp32 -> [B,H,W] fp32
#define CCH 32
#define HH  1024
#define WW  1024
#define RAD 25    // kernel_radius = W // 40 = 25 (window = 51)
#define RPB 2     // rows per block in kernel A
#define PAD 32    // zero-pad rows above/below each image in scratch (>= RAD+1)
#define HP  (HH + 2 * PAD)

// padded scratch: channel-summed + box-w'd intermediate, with zero halo rows
__device__ float g_scratch[4 * HP * WW];

__device__ __forceinline__ float sqrt_approx(float s) {
    float r;
    asm("sqrt.approx.f32 %0, %1;" : "=f"(r) : "f"(s));
    return r;   // sqrt.approx(0) = 0, no NaN guard needed
}

// ---------------------------------------------------------------------------
// Kernel P: zero the halo rows of g_scratch (1 MB, ~1us)
// ---------------------------------------------------------------------------
__global__ __launch_bounds__(256) void pad_zero_kernel() {
    // total pad floats: 4 images * 2*PAD rows * WW = 262144 -> 65536 float4
    int i = blockIdx.x * 256 + threadIdx.x;        // float4 index, grid covers all
    int img   = i / (2 * PAD * WW / 4);            // 16384 float4 per image pad
    int rem   = i % (2 * PAD * WW / 4);
    int row   = rem / (WW / 4);                    // 0..63
    int col4  = rem % (WW / 4);
    int prow  = (row < PAD) ? row : (HH + PAD + row - PAD);  // front or back halo
    float4* p = reinterpret_cast<float4*>(g_scratch + ((size_t)img * HP + prow) * WW) + col4;
    *p = make_float4(0.f, 0.f, 0.f, 0.f);
}

// ---------------------------------------------------------------------------
// Kernel D: dummy (shifts ncu's -s 5 capture onto kernel A)
// ---------------------------------------------------------------------------
__global__ void dummy_kernel() {}

// ---------------------------------------------------------------------------
// Kernel A: per (b, 2-row tile) — gradient magnitude, channel sum, box-w.
// 256 threads; thread owns 4 consecutive w (float4) for both rows.
// Front-batched loads (prev + cur0 + cur1 + left0 + left1 = 5 independent),
// sqrt.approx (no guard), modest registers for high occupancy.
// ---------------------------------------------------------------------------
__global__ __launch_bounds__(256) void grad_boxw_kernel(const float* __restrict__ x) {
    const int h0   = blockIdx.x * RPB;
    const int b    = blockIdx.y;
    const int tid  = threadIdx.x;
    const int lane = tid & 31;
    const int wid  = tid >> 5;
    const int w0   = tid << 2;

    const float* xb = x + (size_t)b * CCH * HH * WW;

    float a00 = 0.f, a01 = 0.f, a02 = 0.f, a03 = 0.f;
    float a10 = 0.f, a11 = 0.f, a12 = 0.f, a13 = 0.f;

    for (int c = 0; c < CCH; ++c) {
        const float* base = xb + (size_t)c * HH * WW;
        const float* row0 = base + (size_t)h0 * WW;
        const float* row1 = row0 + WW;

        // ---- front-batched independent loads ----
        float4 prev = (h0 > 0) ? *reinterpret_cast<const float4*>(row0 - WW + w0)
                               : make_float4(0.f, 0.f, 0.f, 0.f);
        float4 c0 = *reinterpret_cast<const float4*>(row0 + w0);
        float4 c1 = *reinterpret_cast<const float4*>(row1 + w0);
        float  l0 = (w0 > 0) ? row0[w0 - 1] : 0.f;
        float  l1 = (w0 > 0) ? row1[w0 - 1] : 0.f;

        // ---- row 0: top=prev, left=l0 ----
        {
            float dx0 = l0   - c0.x;
            float dx1 = c0.x - c0.y;
            float dx2 = c0.y - c0.z;
            float dx3 = c0.z - c0.w;
            float dy0 = prev.x - c0.x;
            float dy1 = prev.y - c0.y;
            float dy2 = prev.z - c0.z;
            float dy3 = prev.w - c0.w;
            a00 += sqrt_approx(dx0 * dx0 + dy0 * dy0);
            a01 += sqrt_approx(dx1 * dx1 + dy1 * dy1);
            a02 += sqrt_approx(dx2 * dx2 + dy2 * dy2);
            a03 += sqrt_approx(dx3 * dx3 + dy3 * dy3);
        }
        // ---- row 1: top=c0, left=l1 ----
        {
            float dx0 = l1   - c1.x;
            float dx1 = c1.x - c1.y;
            float dx2 = c1.y - c1.z;
            float dx3 = c1.z - c1.w;
            float dy0 = c0.x - c1.x;
            float dy1 = c0.y - c1.y;
            float dy2 = c0.z - c1.z;
            float dy3 = c0.w - c1.w;
            a10 += sqrt_approx(dx0 * dx0 + dy0 * dy0);
            a11 += sqrt_approx(dx1 * dx1 + dy1 * dy1);
            a12 += sqrt_approx(dx2 * dx2 + dy2 * dy2);
            a13 += sqrt_approx(dx3 * dx3 + dy3 * dy3);
        }
    }

    // ---- per-row block prefix sum + box-w, 2 rows sequentially ----
    __shared__ float S[WW + 1];
    __shared__ float wsum[8];

    float* gb = g_scratch + (size_t)b * HP * WW + (size_t)PAD * WW;

    #pragma unroll 1
    for (int r = 0; r < RPB; ++r) {
        float v0 = (r == 0) ? a00 : a10;
        float v1 = (r == 0) ? a01 : a11;
        float v2 = (r == 0) ? a02 : a12;
        float v3 = (r == 0) ? a03 : a13;

        float p0 = v0;
        float p1 = p0 + v1;
        float p2 = p1 + v2;
        float p3 = p2 + v3;
        float t  = p3;

        // inclusive warp scan of t
        float sc = t;
        #pragma unroll
        for (int o = 1; o < 32; o <<= 1) {
            float v = __shfl_up_sync(0xffffffffu, sc, o);
            if (lane >= o) sc += v;
        }
        if (lane == 31) wsum[wid] = sc;
        __syncthreads();
        if (wid == 0) {
            float wv = (lane < 8) ? wsum[lane] : 0.f;
            float ws = wv;
            #pragma unroll
            for (int o = 1; o < 8; o <<= 1) {
                float v = __shfl_up_sync(0xffffffffu, ws, o);
                if (lane >= o) ws += v;
            }
            if (lane < 8) wsum[lane] = ws - wv;  // exclusive warp offsets
        }
        __syncthreads();

        float bofs = wsum[wid] + (sc - t);
        if (tid == 0) S[0] = 0.f;
        S[w0 + 1] = bofs + p0;
        S[w0 + 2] = bofs + p1;
        S[w0 + 3] = bofs + p2;
        S[w0 + 4] = bofs + p3;
        __syncthreads();

        float* grow = gb + (size_t)(h0 + r) * WW;
        #pragma unroll
        for (int i = 0; i < 4; ++i) {
            int w  = w0 + i;
            int lo = max(0, w - RAD);
            int hi = min(WW - 1, w + RAD);
            grow[w] = S[hi + 1] - S[lo];
        }
        __syncthreads();
    }
}

// ---------------------------------------------------------------------------
// Kernel B: box filter along h. Padded scratch -> branch-free sliding window,
// fully unrolled so ptxas batches the loads (high MLP).
// ---------------------------------------------------------------------------
#define HT 16
#define W2 (WW / 2)
__global__ __launch_bounds__(256) void boxh_kernel(float* __restrict__ out) {
    const int c2 = blockIdx.x * 256 + threadIdx.x;   // float2 column index
    const int h0 = blockIdx.y * HT;
    const int b  = blockIdx.z;

    const float2* gp = reinterpret_cast<const float2*>(
        g_scratch + ((size_t)b * HP + PAD) * WW) + c2;   // row 0 of the image
    float2* op = reinterpret_cast<float2*>(out + (size_t)b * HH * WW) + c2;

    // window init over [h0-RAD, h0+RAD] — always in-bounds thanks to halo
    float2 t0 = make_float2(0.f, 0.f);
    float2 t1 = make_float2(0.f, 0.f);
    float2 t2 = make_float2(0.f, 0.f);
    float2 t3 = make_float2(0.f, 0.f);
    #pragma unroll
    for (int j = 0; j < 48; j += 4) {
        float2 v0 = gp[(size_t)(h0 - RAD + j + 0) * W2];
        float2 v1 = gp[(size_t)(h0 - RAD + j + 1) * W2];
        float2 v2 = gp[(size_t)(h0 - RAD + j + 2) * W2];
        float2 v3 = gp[(size_t)(h0 - RAD + j + 3) * W2];
        t0.x += v0.x; t0.y += v0.y;
        t1.x += v1.x; t1.y += v1.y;
        t2.x += v2.x; t2.y += v2.y;
        t3.x += v3.x; t3.y += v3.y;
    }
    {
        float2 v0 = gp[(size_t)(h0 + RAD - 2) * W2];
        float2 v1 = gp[(size_t)(h0 + RAD - 1) * W2];
        float2 v2 = gp[(size_t)(h0 + RAD) * W2];
        t0.x += v0.x; t0.y += v0.y;
        t1.x += v1.x; t1.y += v1.y;
        t2.x += v2.x; t2.y += v2.y;
    }
    float2 s;
    s.x = (t0.x + t1.x) + (t2.x + t3.x);
    s.y = (t0.y + t1.y) + (t2.y + t3.y);

    // branch-free sliding window (halo rows are zero)
    #pragma unroll
    for (int i = 0; i < HT; ++i) {
        const int h = h0 + i;
        op[(size_t)h * W2] = s;
        float2 va = gp[(size_t)(h + RAD + 1) * W2];
        float2 vs = gp[(size_t)(h - RAD) * W2];
        s.x += va.x - vs.x;
        s.y += va.y - vs.y;
    }
}

// ---------------------------------------------------------------------------

extern "C" void kernel_launch(void* const* d_in, const int* in_sizes, int n_in,
                              void* d_out, int out_size) {
    const float* x = (const float*)d_in[0];
    float* out = (float*)d_out;

    const int n = in_sizes[0];
    const int B = n / (CCH * HH * WW);   // 4

    dim3 gridA(HH / RPB, B);
    grad_boxw_kernel<<<gridA, 256>>>(x);

    pad_zero_kernel<<<(B * 2 * PAD * WW / 4) / 256, 256>>>();

    dim3 gridB(W2 / 256, HH / HT, B);
    boxh_kernel<<<gridB, 256>>>(out);

    // two dummies -> 5 launches per call so ncu (-s 5) profiles kernel A
    dummy_kernel<<<1, 1>>>();
    dummy_kernel<<<1, 1>>>();
}

// round 6
// speedup vs baseline: 1.7351x; 1.1246x over previous
#include <cuda_runtime.h>

// Shapes fixed by the problem: [B=4, C=32, H=1024, W=1024] fp32 -> [B,H,W] fp32
#define CCH 32
#define HH  1024
#define WW  1024
#define RAD 25    // kernel_radius = W // 40 = 25 (window = 51)
#define RPB 2     // rows per block in kernel A
#define PAD 32    // zero-pad rows above/below each image in scratch (>= RAD+1)
#define HP  (HH + 2 * PAD)

// padded scratch: channel-summed + box-w'd intermediate, with zero halo rows
__device__ float g_scratch[4 * HP * WW];

__device__ __forceinline__ float sqrt_approx(float s) {
    float r;
    asm("sqrt.approx.f32 %0, %1;" : "=f"(r) : "f"(s));
    return r;   // sqrt.approx(0) = 0, no NaN guard needed
}

// ---------------------------------------------------------------------------
// Kernel A: per (b, 2-row tile) — gradient magnitude, channel sum, box-w.
// 256 threads; thread owns 4 consecutive w (float4) for both rows.
// Software-pipelined channel loop: iteration c+1's loads are issued before
// iteration c's compute, giving each load ~1 iteration of latency slack.
// Blocks 0..63 of each image also zero one halo row (fuses the pad kernel).
// ---------------------------------------------------------------------------
__global__ __launch_bounds__(256) void grad_boxw_kernel(const float* __restrict__ x) {
    const int h0   = blockIdx.x * RPB;
    const int b    = blockIdx.y;
    const int tid  = threadIdx.x;
    const int lane = tid & 31;
    const int wid  = tid >> 5;
    const int w0   = tid << 2;

    // ---- fused halo zeroing: first 64 blocks of each image zero 1 halo row ----
    if (blockIdx.x < 2 * PAD) {
        int row  = blockIdx.x;                         // 0..63
        int prow = (row < PAD) ? row : (HH + row);     // top 0..31, bottom HP-32..HP-1
        float4* p = reinterpret_cast<float4*>(g_scratch + ((size_t)b * HP + prow) * WW);
        p[tid] = make_float4(0.f, 0.f, 0.f, 0.f);      // 256 float4 = one row
    }

    const float* xb = x + (size_t)b * CCH * HH * WW;

    float a00 = 0.f, a01 = 0.f, a02 = 0.f, a03 = 0.f;
    float a10 = 0.f, a11 = 0.f, a12 = 0.f, a13 = 0.f;

    const bool has_top  = (h0 > 0);
    const bool has_left = (w0 > 0);

    // ---- prologue: loads for channel 0 ----
    const float* base = xb;   // c = 0
    const float* row0 = base + (size_t)h0 * WW;
    const float* row1 = row0 + WW;
    float4 prev = has_top ? *reinterpret_cast<const float4*>(row0 - WW + w0)
                          : make_float4(0.f, 0.f, 0.f, 0.f);
    float4 c0 = *reinterpret_cast<const float4*>(row0 + w0);
    float4 c1 = *reinterpret_cast<const float4*>(row1 + w0);
    float  l0 = has_left ? row0[w0 - 1] : 0.f;
    float  l1 = has_left ? row1[w0 - 1] : 0.f;

    for (int c = 0; c < CCH; ++c) {
        // ---- prefetch next channel (independent of current compute) ----
        float4 nprev = make_float4(0.f, 0.f, 0.f, 0.f);
        float4 nc0, nc1;
        float  nl0 = 0.f, nl1 = 0.f;
        if (c + 1 < CCH) {
            const float* nbase = xb + (size_t)(c + 1) * HH * WW;
            const float* nrow0 = nbase + (size_t)h0 * WW;
            const float* nrow1 = nrow0 + WW;
            if (has_top) nprev = *reinterpret_cast<const float4*>(nrow0 - WW + w0);
            nc0 = *reinterpret_cast<const float4*>(nrow0 + w0);
            nc1 = *reinterpret_cast<const float4*>(nrow1 + w0);
            if (has_left) { nl0 = nrow0[w0 - 1]; nl1 = nrow1[w0 - 1]; }
        } else {
            nc0 = nc1 = make_float4(0.f, 0.f, 0.f, 0.f);
        }

        // ---- compute current channel ----
        {
            float dx0 = l0   - c0.x;
            float dx1 = c0.x - c0.y;
            float dx2 = c0.y - c0.z;
            float dx3 = c0.z - c0.w;
            float dy0 = prev.x - c0.x;
            float dy1 = prev.y - c0.y;
            float dy2 = prev.z - c0.z;
            float dy3 = prev.w - c0.w;
            a00 += sqrt_approx(dx0 * dx0 + dy0 * dy0);
            a01 += sqrt_approx(dx1 * dx1 + dy1 * dy1);
            a02 += sqrt_approx(dx2 * dx2 + dy2 * dy2);
            a03 += sqrt_approx(dx3 * dx3 + dy3 * dy3);
        }
        {
            float dx0 = l1   - c1.x;
            float dx1 = c1.x - c1.y;
            float dx2 = c1.y - c1.z;
            float dx3 = c1.z - c1.w;
            float dy0 = c0.x - c1.x;
            float dy1 = c0.y - c1.y;
            float dy2 = c0.z - c1.z;
            float dy3 = c0.w - c1.w;
            a10 += sqrt_approx(dx0 * dx0 + dy0 * dy0);
            a11 += sqrt_approx(dx1 * dx1 + dy1 * dy1);
            a12 += sqrt_approx(dx2 * dx2 + dy2 * dy2);
            a13 += sqrt_approx(dx3 * dx3 + dy3 * dy3);
        }

        prev = nprev; c0 = nc0; c1 = nc1; l0 = nl0; l1 = nl1;
    }

    // ---- per-row block prefix sum + box-w, 2 rows sequentially ----
    __shared__ float S[WW + 1];
    __shared__ float wsum[8];

    float* gb = g_scratch + (size_t)b * HP * WW + (size_t)PAD * WW;

    #pragma unroll 1
    for (int r = 0; r < RPB; ++r) {
        float v0 = (r == 0) ? a00 : a10;
        float v1 = (r == 0) ? a01 : a11;
        float v2 = (r == 0) ? a02 : a12;
        float v3 = (r == 0) ? a03 : a13;

        float p0 = v0;
        float p1 = p0 + v1;
        float p2 = p1 + v2;
        float p3 = p2 + v3;
        float t  = p3;

        // inclusive warp scan of t
        float sc = t;
        #pragma unroll
        for (int o = 1; o < 32; o <<= 1) {
            float v = __shfl_up_sync(0xffffffffu, sc, o);
            if (lane >= o) sc += v;
        }
        if (lane == 31) wsum[wid] = sc;
        __syncthreads();
        if (wid == 0) {
            float wv = (lane < 8) ? wsum[lane] : 0.f;
            float ws = wv;
            #pragma unroll
            for (int o = 1; o < 8; o <<= 1) {
                float v = __shfl_up_sync(0xffffffffu, ws, o);
                if (lane >= o) ws += v;
            }
            if (lane < 8) wsum[lane] = ws - wv;  // exclusive warp offsets
        }
        __syncthreads();

        float bofs = wsum[wid] + (sc - t);
        if (tid == 0) S[0] = 0.f;
        S[w0 + 1] = bofs + p0;
        S[w0 + 2] = bofs + p1;
        S[w0 + 3] = bofs + p2;
        S[w0 + 4] = bofs + p3;
        __syncthreads();

        float* grow = gb + (size_t)(h0 + r) * WW;
        #pragma unroll
        for (int i = 0; i < 4; ++i) {
            int w  = w0 + i;
            int lo = max(0, w - RAD);
            int hi = min(WW - 1, w + RAD);
            grow[w] = S[hi + 1] - S[lo];
        }
        __syncthreads();
    }
}

// ---------------------------------------------------------------------------
// Kernel B: box filter along h. Padded scratch -> branch-free sliding window,
// fully unrolled so ptxas batches the loads (high MLP).
// ---------------------------------------------------------------------------
#define HT 16
#define W2 (WW / 2)
__global__ __launch_bounds__(256) void boxh_kernel(float* __restrict__ out) {
    const int c2 = blockIdx.x * 256 + threadIdx.x;   // float2 column index
    const int h0 = blockIdx.y * HT;
    const int b  = blockIdx.z;

    const float2* gp = reinterpret_cast<const float2*>(
        g_scratch + ((size_t)b * HP + PAD) * WW) + c2;   // row 0 of the image
    float2* op = reinterpret_cast<float2*>(out + (size_t)b * HH * WW) + c2;

    // window init over [h0-RAD, h0+RAD] — always in-bounds thanks to halo
    float2 t0 = make_float2(0.f, 0.f);
    float2 t1 = make_float2(0.f, 0.f);
    float2 t2 = make_float2(0.f, 0.f);
    float2 t3 = make_float2(0.f, 0.f);
    #pragma unroll
    for (int j = 0; j < 48; j += 4) {
        float2 v0 = gp[(size_t)(h0 - RAD + j + 0) * W2];
        float2 v1 = gp[(size_t)(h0 - RAD + j + 1) * W2];
        float2 v2 = gp[(size_t)(h0 - RAD + j + 2) * W2];
        float2 v3 = gp[(size_t)(h0 - RAD + j + 3) * W2];
        t0.x += v0.x; t0.y += v0.y;
        t1.x += v1.x; t1.y += v1.y;
        t2.x += v2.x; t2.y += v2.y;
        t3.x += v3.x; t3.y += v3.y;
    }
    {
        float2 v0 = gp[(size_t)(h0 + RAD - 2) * W2];
        float2 v1 = gp[(size_t)(h0 + RAD - 1) * W2];
        float2 v2 = gp[(size_t)(h0 + RAD) * W2];
        t0.x += v0.x; t0.y += v0.y;
        t1.x += v1.x; t1.y += v1.y;
        t2.x += v2.x; t2.y += v2.y;
    }
    float2 s;
    s.x = (t0.x + t1.x) + (t2.x + t3.x);
    s.y = (t0.y + t1.y) + (t2.y + t3.y);

    // branch-free sliding window (halo rows are zero)
    #pragma unroll
    for (int i = 0; i < HT; ++i) {
        const int h = h0 + i;
        op[(size_t)h * W2] = s;
        float2 va = gp[(size_t)(h + RAD + 1) * W2];
        float2 vs = gp[(size_t)(h - RAD) * W2];
        s.x += va.x - vs.x;
        s.y += va.y - vs.y;
    }
}

// ---------------------------------------------------------------------------

extern "C" void kernel_launch(void* const* d_in, const int* in_sizes, int n_in,
                              void* d_out, int out_size) {
    const float* x = (const float*)d_in[0];
    float* out = (float*)d_out;

    const int n = in_sizes[0];
    const int B = n / (CCH * HH * WW);   // 4

    dim3 gridA(HH / RPB, B);
    grad_boxw_kernel<<<gridA, 256>>>(x);

    dim3 gridB(W2 / 256, HH / HT, B);
    boxh_kernel<<<gridB, 256>>>(out);
}